// round 6
// baseline (speedup 1.0000x reference)
#include <cuda_runtime.h>

#define NB 128
#define NT 1024
#define ND 3
#define NH 512
#define NC 3
#define NSLICE 16      // h-slices per batch group (CTAs that must sync)
#define HS 32          // h per slice
#define NGRP 16        // batch groups (8 rows each); CTA serves 2 groups
#define BGr 8          // batch rows per group
#define KS 32          // k per k-slice (per warp)
#define NKS 16         // k-slices = warps
#define THREADS 512

typedef unsigned long long u64;

// sense-reversing barrier state, one slot per (group, step).
// Zero-initialized at load; self-restoring across graph replays:
// cnt returns to 0 each use, flag flips each use (pollers compare to entry value).
__device__ int g_cnt [NGRP * NT];
__device__ int g_flag[NGRP * NT];

static __device__ __forceinline__ u64 pack2(float x, float y) {
    u64 v; asm("mov.b64 %0, {%1, %2};" : "=l"(v) : "f"(x), "f"(y)); return v;
}
static __device__ __forceinline__ float2 unpack2(u64 v) {
    float2 f; asm("mov.b64 {%0, %1}, %2;" : "=f"(f.x), "=f"(f.y) : "l"(v)); return f;
}
static __device__ __forceinline__ u64 ffma2(u64 a, u64 b, u64 c) {
    u64 d; asm("fma.rn.f32x2 %0, %1, %2, %3;" : "=l"(d) : "l"(a), "l"(b), "l"(c)); return d;
}
static __device__ __forceinline__ u64 fadd2(u64 a, u64 b) {
    u64 d; asm("add.rn.f32x2 %0, %1, %2;" : "=l"(d) : "l"(a), "l"(b)); return d;
}

// tid0 only. Returns 1 if this CTA was the last arriver (wait may be skipped:
// the acq_rel RMW that observed all other arrivals provides acquire ordering).
static __device__ __forceinline__ int barrier_arrive(int slot, int* sense) {
    int* pc = &g_cnt[slot];
    int* pf = &g_flag[slot];
    int S;
    asm volatile("ld.relaxed.gpu.global.s32 %0, [%1];" : "=r"(S) : "l"(pf));
    *sense = S;
    int old;
    asm volatile("atom.acq_rel.gpu.global.add.s32 %0, [%1], 1;"
                 : "=r"(old) : "l"(pc) : "memory");
    if (old == NSLICE - 1) {
        asm volatile("st.relaxed.gpu.global.s32 [%0], 0;" :: "l"(pc) : "memory");
        asm volatile("st.release.gpu.global.s32 [%0], %1;" :: "l"(pf), "r"(S ^ 1) : "memory");
        return 1;
    }
    return 0;
}
static __device__ __forceinline__ void barrier_wait(int slot, int S) {
    int* pf = &g_flag[slot];
    int v;
    do {
        asm volatile("ld.acquire.gpu.global.s32 %0, [%1];"
                     : "=r"(v) : "l"(pf) : "memory");
    } while (v == S);
}

extern __shared__ float smem_f[];

// One persistent kernel. blockIdx: pair = bid/16, slice = bid%16.
// CTA serves two batch groups gA=2*pair, gB=2*pair+1 (8 rows each), same
// h-slice -> same weights (held in registers). The two groups' barrier
// latencies are hidden behind each other's compute phases.
__global__ void __launch_bounds__(THREADS, 1)
flipflop_main(const float* __restrict__ inputs,
              const float* __restrict__ Wv,
              const float* __restrict__ Pv,
              const float* __restrict__ bv,
              const float* __restrict__ Wz,
              const float* __restrict__ Pz,
              const float* __restrict__ bz,
              const float* __restrict__ fcW,
              const float* __restrict__ fcb,
              float* __restrict__ out,
              float* __restrict__ hidden)
{
    float* rA   = smem_f;                         // [BGr*NH] 16 KB
    float* rB   = smem_f + BGr * NH;              // [BGr*NH] 16 KB
    u64*   psum = (u64*)(smem_f + 2 * BGr * NH);  // [BGr*NKS*HS] 32 KB (shared A/B)

    const int tid   = threadIdx.x;
    const int pair  = blockIdx.x >> 4;
    const int slice = blockIdx.x & 15;
    const int gA    = pair * 2, gB = gA + 1;
    const int gbA   = gA * BGr, gbB = gB * BGr;
    const int ks    = tid >> 5;
    const int hh    = tid & 31;
    const int hg    = slice * HS + hh;

    // ---- weight slice into registers: k-pairs, z and v separate ----
    u64 wz[16], wv[16];
    {
        const u64* zr = (const u64*)(Wz + (size_t)hg * NH + ks * KS);
        const u64* vr = (const u64*)(Wv + (size_t)hg * NH + ks * KS);
        #pragma unroll
        for (int j = 0; j < 16; ++j) { wz[j] = zr[j]; wv[j] = vr[j]; }
    }

    // ---- reduce-role constants (threads 0..255: rb = tid>>5 in [0,8)) ----
    const int rb = tid >> 5;
    const float pz0 = Pz[hg*3+0], pz1 = Pz[hg*3+1], pz2 = Pz[hg*3+2];
    float pm0 = 0.f, pm1 = 0.f, pm2 = 0.f;        // P_m: bottom half zeroed
    if (hg < NH/2) { pm0 = Pv[hg*3+0]; pm1 = Pv[hg*3+1]; pm2 = Pv[hg*3+2]; }
    const float bzr = bz[hg];
    const float bvr = bv[hg];

    // reload-role constants: thread loads 2 float4 of its group's r
    const int rl_row = tid >> 6;                  // [0,8)
    const int rl_c4  = (tid & 63) * 2;            // float4 index [0,128) step 2

    // r0 = 0 for both groups
    for (int i = tid; i < 2 * BGr * NH; i += THREADS) smem_f[i] = 0.f;
    __syncthreads();

    int senseA = 0, senseB = 0, lastA = 0, lastB = 0;

    for (int t = 0; t < NT; ++t) {
        // ===================== group A =====================
        float xa0 = 0.f, xa1 = 0.f, xa2 = 0.f;
        if (tid < 256) {
            const float* xp = inputs + ((size_t)(gbA + rb) * NT + t) * ND;
            xa0 = xp[0]; xa1 = xp[1]; xa2 = xp[2];
        }
        // compute: partial (z,v) dot-products over this warp's k-slice
        #pragma unroll 1
        for (int b = 0; b < BGr; ++b) {
            const ulonglong2* rp = (const ulonglong2*)(rA + b * NH + ks * KS);
            u64 az0 = 0ull, az1 = 0ull, av0 = 0ull, av1 = 0ull;
            #pragma unroll
            for (int kk = 0; kk < 8; ++kk) {
                ulonglong2 rr = rp[kk];
                az0 = ffma2(rr.x, wz[kk*2+0], az0);
                av0 = ffma2(rr.x, wv[kk*2+0], av0);
                az1 = ffma2(rr.y, wz[kk*2+1], az1);
                av1 = ffma2(rr.y, wv[kk*2+1], av1);
            }
            const float2 fz = unpack2(fadd2(az0, az1));
            const float2 fv = unpack2(fadd2(av0, av1));
            psum[(b * NKS + ks) * HS + hh] = pack2(fz.x + fz.y, fv.x + fv.y);
        }
        __syncthreads();
        if (tid < 256) {
            float sz = 0.f, sv = 0.f;
            #pragma unroll
            for (int k = 0; k < NKS; ++k) {
                float2 p = unpack2(psum[(rb * NKS + k) * HS + hh]);
                sz += p.x; sv += p.y;
            }
            const float az = sz + xa0*pz0 + xa1*pz1 + xa2*pz2 + bzr;
            const float av = sv + xa0*pm0 + xa1*pm1 + xa2*pm2 + bvr;
            const float z  = 1.f / (1.f + __expf(-az));
            const float c  = 1.f / (1.f + __expf(-av));
            const float ro = rA[rb * NH + hg];
            hidden[((size_t)(gbA + rb) * NT + t) * NH + hg] = fmaf(z, c - ro, ro);
        }
        __syncthreads();
        if (tid == 0) lastA = barrier_arrive(gA * NT + t, &senseA);

        // overlapped: finish group B's previous step (wait + reload)
        if (t > 0) {
            if (tid == 0 && !lastB) barrier_wait(gB * NT + (t - 1), senseB);
            __syncthreads();
            const float4* s = (const float4*)(hidden + ((size_t)(gbB + rl_row) * NT + (t - 1)) * NH);
            float4*       d = (float4*)(rB + rl_row * NH);
            d[rl_c4]     = s[rl_c4];
            d[rl_c4 + 1] = s[rl_c4 + 1];
            __syncthreads();
        }

        // ===================== group B =====================
        float xb0 = 0.f, xb1 = 0.f, xb2 = 0.f;
        if (tid < 256) {
            const float* xp = inputs + ((size_t)(gbB + rb) * NT + t) * ND;
            xb0 = xp[0]; xb1 = xp[1]; xb2 = xp[2];
        }
        #pragma unroll 1
        for (int b = 0; b < BGr; ++b) {
            const ulonglong2* rp = (const ulonglong2*)(rB + b * NH + ks * KS);
            u64 az0 = 0ull, az1 = 0ull, av0 = 0ull, av1 = 0ull;
            #pragma unroll
            for (int kk = 0; kk < 8; ++kk) {
                ulonglong2 rr = rp[kk];
                az0 = ffma2(rr.x, wz[kk*2+0], az0);
                av0 = ffma2(rr.x, wv[kk*2+0], av0);
                az1 = ffma2(rr.y, wz[kk*2+1], az1);
                av1 = ffma2(rr.y, wv[kk*2+1], av1);
            }
            const float2 fz = unpack2(fadd2(az0, az1));
            const float2 fv = unpack2(fadd2(av0, av1));
            psum[(b * NKS + ks) * HS + hh] = pack2(fz.x + fz.y, fv.x + fv.y);
        }
        __syncthreads();
        if (tid < 256) {
            float sz = 0.f, sv = 0.f;
            #pragma unroll
            for (int k = 0; k < NKS; ++k) {
                float2 p = unpack2(psum[(rb * NKS + k) * HS + hh]);
                sz += p.x; sv += p.y;
            }
            const float az = sz + xb0*pz0 + xb1*pz1 + xb2*pz2 + bzr;
            const float av = sv + xb0*pm0 + xb1*pm1 + xb2*pm2 + bvr;
            const float z  = 1.f / (1.f + __expf(-az));
            const float c  = 1.f / (1.f + __expf(-av));
            const float ro = rB[rb * NH + hg];
            hidden[((size_t)(gbB + rb) * NT + t) * NH + hg] = fmaf(z, c - ro, ro);
        }
        __syncthreads();
        if (tid == 0) lastB = barrier_arrive(gB * NT + t, &senseB);

        // finish group A's current step (wait + reload); arrive->wait gap =
        // group B's whole compute+reduce, so the poll should hit immediately.
        if (tid == 0 && !lastA) barrier_wait(gA * NT + t, senseA);
        __syncthreads();
        if (t + 1 < NT) {
            const float4* s = (const float4*)(hidden + ((size_t)(gbA + rl_row) * NT + t) * NH);
            float4*       d = (float4*)(rA + rl_row * NH);
            d[rl_c4]     = s[rl_c4];
            d[rl_c4 + 1] = s[rl_c4 + 1];
            __syncthreads();
        }
    }
    if (tid == 0 && !lastB) barrier_wait(gB * NT + (NT - 1), senseB);
    __syncthreads();

    // ================= fc epilogue =================
    // Both groups' hidden complete. CTA covers its 16 rows (2 groups x 8),
    // t in [slice*64, slice*64+64). warp w -> row; shuffle-reduce over H.
    float* fw = rA;                               // reuse smem (r dead)
    for (int i = tid; i < NC * NH; i += THREADS) fw[i] = fcW[i];
    const float fb0 = fcb[0], fb1 = fcb[1], fb2 = fcb[2];
    __syncthreads();

    float4 fw0[4], fw1[4], fw2[4];
    #pragma unroll
    for (int j = 0; j < 4; ++j) {
        const int i = hh + j * 32;
        fw0[j] = ((const float4*)(fw + 0 * NH))[i];
        fw1[j] = ((const float4*)(fw + 1 * NH))[i];
        fw2[j] = ((const float4*)(fw + 2 * NH))[i];
    }

    const int w   = tid >> 5;
    const int row = (w < 8) ? (gbA + w) : (gbB + (w - 8));
    const int t0  = slice * (NT / NSLICE);
    const float* hp = hidden + ((size_t)row * NT + t0) * NH;
    float*       op = out    + ((size_t)row * NT + t0) * NC;

    for (int it = 0; it < NT / NSLICE; ++it) {
        const float4* h4 = (const float4*)(hp + (size_t)it * NH);
        float a0 = 0.f, a1 = 0.f, a2 = 0.f;
        #pragma unroll
        for (int j = 0; j < 4; ++j) {
            float4 h = h4[hh + j * 32];
            a0 += h.x*fw0[j].x + h.y*fw0[j].y + h.z*fw0[j].z + h.w*fw0[j].w;
            a1 += h.x*fw1[j].x + h.y*fw1[j].y + h.z*fw1[j].z + h.w*fw1[j].w;
            a2 += h.x*fw2[j].x + h.y*fw2[j].y + h.z*fw2[j].z + h.w*fw2[j].w;
        }
        #pragma unroll
        for (int o = 16; o; o >>= 1) {
            a0 += __shfl_down_sync(0xffffffffu, a0, o);
            a1 += __shfl_down_sync(0xffffffffu, a1, o);
            a2 += __shfl_down_sync(0xffffffffu, a2, o);
        }
        if (hh == 0) {
            op[it*3+0] = a0 + fb0;
            op[it*3+1] = a1 + fb1;
            op[it*3+2] = a2 + fb2;
        }
    }
}

extern "C" void kernel_launch(void* const* d_in, const int* in_sizes, int n_in,
                              void* d_out, int out_size)
{
    const float* inputs = (const float*)d_in[0];
    const float* Wv     = (const float*)d_in[1];
    const float* Pv     = (const float*)d_in[2];
    const float* b_v    = (const float*)d_in[3];
    const float* Wz     = (const float*)d_in[4];
    const float* Pz     = (const float*)d_in[5];
    const float* b_z    = (const float*)d_in[6];
    const float* fcW    = (const float*)d_in[7];
    const float* fcb    = (const float*)d_in[8];

    // outputs concatenated in reference return order: out (B,T,C) then hidden (B,T,H)
    float* out    = (float*)d_out;
    float* hidden = out + (size_t)NB * NT * NC;

    const int smem_bytes = 2 * BGr * NH * 4 + BGr * NKS * HS * 8;   // 32KB + 32KB
    cudaFuncSetAttribute(flipflop_main,
                         cudaFuncAttributeMaxDynamicSharedMemorySize, smem_bytes);

    flipflop_main<<<(NGRP / 2) * NSLICE, THREADS, smem_bytes>>>(
        inputs, Wv, Pv, b_v, Wz, Pz, b_z, fcW, fcb, out, hidden);
}